// round 1
// baseline (speedup 1.0000x reference)
#include <cuda_runtime.h>

// ---------------------------------------------------------------------------
// MetaMLP (3-step GraphNet / MetaLayer) on GB300.
//
// Per step t:
//   ea'   = relu( xW1[src] + xW2[dst] + ea @ We3 + uW4b[batch[src]] )   (edge)
//   agg   = segment_mean(ea', dst)                                       (atomics)
//   x'    = relu( [x, agg] @ Wn12 + uWn3b[batch] )                       (node)
//   u'    = relu( [u, segment_mean(x', batch)] @ W_glob + b_glob )       (global)
//
// x_t written into d_out x-section (50000 x 512) at col 128*t,
// u_t written into d_out global-section (16 x 512) at col 128*t.
// ---------------------------------------------------------------------------

#define D 128
static constexpr int N_NODES  = 50000;
static constexpr int N_EDGES  = 800000;
static constexpr int N_GRAPHS = 16;
static constexpr int OUTW     = 4 * D;   // 512 output columns per row

// ------------------------- device scratch (no allocs) ----------------------
__device__ float g_ea  [(size_t)N_EDGES  * D];      // current edge features
__device__ float g_P12 [(size_t)N_NODES  * 2 * D];  // [P1 | P2] per node
__device__ float g_agg [(size_t)N_NODES  * D];      // sum of incoming ea'
__device__ float g_u    [N_GRAPHS * D];             // current u
__device__ float g_uW4b [N_GRAPHS * D];             // u@We4 + b_edge
__device__ float g_uWn3b[N_GRAPHS * D];             // u@Wn3 + b_node
__device__ float g_gsum [N_GRAPHS * D];             // per-graph node sums
__device__ float g_invN [N_NODES];                  // 1/max(in-degree,1)
__device__ float g_invG [N_GRAPHS];                 // 1/max(nodes per graph,1)

// ------------------------------ helpers ------------------------------------
__device__ __forceinline__ void fma4x4(float4& acc, float4 a,
                                       float4 w0, float4 w1, float4 w2, float4 w3) {
    acc.x = fmaf(a.x, w0.x, fmaf(a.y, w1.x, fmaf(a.z, w2.x, fmaf(a.w, w3.x, acc.x))));
    acc.y = fmaf(a.x, w0.y, fmaf(a.y, w1.y, fmaf(a.z, w2.y, fmaf(a.w, w3.y, acc.y))));
    acc.z = fmaf(a.x, w0.z, fmaf(a.y, w1.z, fmaf(a.z, w2.z, fmaf(a.w, w3.z, acc.z))));
    acc.w = fmaf(a.x, w0.w, fmaf(a.y, w1.w, fmaf(a.z, w2.w, fmaf(a.w, w3.w, acc.w))));
}

// ------------------------------ init / counts ------------------------------
__global__ void init_kernel(const float* __restrict__ x, const float* __restrict__ u,
                            float* __restrict__ out_x, float* __restrict__ out_g) {
    int stride = gridDim.x * blockDim.x;
    int tid0 = blockIdx.x * blockDim.x + threadIdx.x;
    for (int i = tid0; i < N_NODES * D; i += stride) {
        int r = i >> 7, c = i & (D - 1);
        out_x[(size_t)r * OUTW + c] = x[i];
    }
    for (int i = tid0; i < N_GRAPHS * D; i += stride) {
        int r = i >> 7, c = i & (D - 1);
        out_g[(size_t)r * OUTW + c] = u[i];
        g_u[i] = u[i];
    }
    for (int i = tid0; i < N_NODES; i += stride) g_invN[i] = 0.f;
    for (int i = tid0; i < N_GRAPHS; i += stride) g_invG[i] = 0.f;
}

__global__ void hist_kernel(const int* __restrict__ dst, const int* __restrict__ batch) {
    int stride = gridDim.x * blockDim.x;
    int tid0 = blockIdx.x * blockDim.x + threadIdx.x;
    for (int i = tid0; i < N_EDGES; i += stride) atomicAdd(&g_invN[dst[i]], 1.f);
    for (int i = tid0; i < N_NODES; i += stride) atomicAdd(&g_invG[batch[i]], 1.f);
}

__global__ void finalize_counts_kernel() {
    int stride = gridDim.x * blockDim.x;
    int tid0 = blockIdx.x * blockDim.x + threadIdx.x;
    for (int i = tid0; i < N_NODES; i += stride) g_invN[i] = 1.f / fmaxf(g_invN[i], 1.f);
    for (int i = tid0; i < N_GRAPHS; i += stride) g_invG[i] = 1.f / fmaxf(g_invG[i], 1.f);
}

__global__ void zero_agg_kernel() {
    int stride = gridDim.x * blockDim.x;
    for (int i = blockIdx.x * blockDim.x + threadIdx.x; i < N_NODES * D; i += stride)
        g_agg[i] = 0.f;
}

// ------------------------ per-step small precompute -------------------------
// uW4b = u @ We4 + b_edge ; uWn3b = u @ Wn3 + b_node ; gsum = 0
__global__ void prep_u_kernel(const float* __restrict__ W_edge, const float* __restrict__ b_edge,
                              const float* __restrict__ W_node, const float* __restrict__ b_node) {
    __shared__ float su[N_GRAPHS * D];
    for (int i = threadIdx.x; i < N_GRAPHS * D; i += blockDim.x) su[i] = g_u[i];
    __syncthreads();
    int j = threadIdx.x;  // 0..127
    float be = b_edge[j], bn = b_node[j];
#pragma unroll
    for (int g = 0; g < N_GRAPHS; g++) {
        float aE = be, aN = bn;
        for (int k = 0; k < D; k++) {
            float ug = su[g * D + k];
            aE = fmaf(ug, W_edge[(3 * D + k) * D + j], aE);
            aN = fmaf(ug, W_node[(2 * D + k) * D + j], aN);
        }
        g_uW4b[g * D + j]  = aE;
        g_uWn3b[g * D + j] = aN;
        g_gsum[g * D + j]  = 0.f;
    }
}

// ----------------------- P1/P2 dense matvec (K=128) ------------------------
// g_P12[row*256 + out_col + j] = X[row] @ W   (W: 128x128 row-major)
__global__ void __launch_bounds__(128) matvec_P_kernel(
    const float* __restrict__ X,   // row stride OUTW
    const float* __restrict__ W,
    int out_col) {
    extern __shared__ float sh[];
    float* sW = sh;           // D*D
    float* sV = sh + D * D;   // 4 warps * 8 rows * D
    for (int i = threadIdx.x; i < D * D; i += blockDim.x) sW[i] = W[i];
    __syncthreads();
    int warp = threadIdx.x >> 5, lane = threadIdx.x & 31;
    float* myV = sV + warp * 8 * D;
    const int groups = N_NODES / 8;
    for (int grp = blockIdx.x * 4 + warp; grp < groups; grp += gridDim.x * 4) {
        int r0 = grp * 8;
#pragma unroll
        for (int e = 0; e < 8; e++) {
            float4 v = *((const float4*)(X + (size_t)(r0 + e) * OUTW) + lane);
            *((float4*)(myV + e * D) + lane) = v;
        }
        __syncwarp();
        float4 acc[8];
#pragma unroll
        for (int e = 0; e < 8; e++) acc[e] = make_float4(0.f, 0.f, 0.f, 0.f);
        for (int k = 0; k < D; k += 4) {
            float4 w0 = *((const float4*)(sW + (k + 0) * D) + lane);
            float4 w1 = *((const float4*)(sW + (k + 1) * D) + lane);
            float4 w2 = *((const float4*)(sW + (k + 2) * D) + lane);
            float4 w3 = *((const float4*)(sW + (k + 3) * D) + lane);
#pragma unroll
            for (int e = 0; e < 8; e++) {
                float4 a = *(const float4*)(myV + e * D + k);
                fma4x4(acc[e], a, w0, w1, w2, w3);
            }
        }
#pragma unroll
        for (int e = 0; e < 8; e++)
            *((float4*)(g_P12 + (size_t)(r0 + e) * (2 * D) + out_col) + lane) = acc[e];
        __syncwarp();
    }
}

// ------------------------------- edge kernel -------------------------------
// ea' = relu(P1[src] + P2[dst] + ea@We3 + uW4b[batch[src]]); scatter-add to agg
__global__ void __launch_bounds__(128) edge_kernel(
    int use_ext, const float* __restrict__ ext_ea,
    const int* __restrict__ src, const int* __restrict__ dst,
    const int* __restrict__ batch,
    const float* __restrict__ We3) {
    extern __shared__ float sh[];
    float* sW  = sh;                      // D*D   = 64KB
    float* sU  = sh + D * D;              // 16*D  = 8KB
    float* sEA = sU + N_GRAPHS * D;       // 4*8*D = 16KB
    for (int i = threadIdx.x; i < D * D; i += blockDim.x) sW[i] = We3[i];
    for (int i = threadIdx.x; i < N_GRAPHS * D; i += blockDim.x) sU[i] = g_uW4b[i];
    __syncthreads();
    const float* ea_in = use_ext ? ext_ea : (const float*)g_ea;
    int warp = threadIdx.x >> 5, lane = threadIdx.x & 31;
    float* myEA = sEA + warp * 8 * D;
    const int groups = N_EDGES / 8;
    for (int grp = blockIdx.x * 4 + warp; grp < groups; grp += gridDim.x * 4) {
        int e0 = grp * 8;
#pragma unroll
        for (int e = 0; e < 8; e++) {
            float4 v = *((const float4*)(ea_in + (size_t)(e0 + e) * D) + lane);
            *((float4*)(myEA + e * D) + lane) = v;
        }
        __syncwarp();
        float4 acc[8];
#pragma unroll
        for (int e = 0; e < 8; e++) acc[e] = make_float4(0.f, 0.f, 0.f, 0.f);
        for (int k = 0; k < D; k += 4) {
            float4 w0 = *((const float4*)(sW + (k + 0) * D) + lane);
            float4 w1 = *((const float4*)(sW + (k + 1) * D) + lane);
            float4 w2 = *((const float4*)(sW + (k + 2) * D) + lane);
            float4 w3 = *((const float4*)(sW + (k + 3) * D) + lane);
#pragma unroll
            for (int e = 0; e < 8; e++) {
                float4 a = *(const float4*)(myEA + e * D + k);
                fma4x4(acc[e], a, w0, w1, w2, w3);
            }
        }
#pragma unroll
        for (int e = 0; e < 8; e++) {
            int ei = e0 + e;
            int s = __ldg(src + ei);
            int d = __ldg(dst + ei);
            int g = __ldg(batch + s);
            float4 p1 = __ldg((const float4*)(g_P12 + (size_t)s * (2 * D)) + lane);
            float4 p2 = __ldg((const float4*)(g_P12 + (size_t)d * (2 * D) + D) + lane);
            float4 ub = *((const float4*)(sU + g * D) + lane);
            float4 r;
            r.x = fmaxf(acc[e].x + p1.x + p2.x + ub.x, 0.f);
            r.y = fmaxf(acc[e].y + p1.y + p2.y + ub.y, 0.f);
            r.z = fmaxf(acc[e].z + p1.z + p2.z + ub.z, 0.f);
            r.w = fmaxf(acc[e].w + p1.w + p2.w + ub.w, 0.f);
            *((float4*)(g_ea + (size_t)ei * D) + lane) = r;
            float* ag = g_agg + (size_t)d * D + lane * 4;
            atomicAdd(ag + 0, r.x);
            atomicAdd(ag + 1, r.y);
            atomicAdd(ag + 2, r.z);
            atomicAdd(ag + 3, r.w);
        }
        __syncwarp();
    }
}

// ------------------------------- node kernel -------------------------------
// x' = relu([x, agg] @ Wn12 + uWn3b[batch]); accumulate per-graph sums
__global__ void __launch_bounds__(256) node_kernel(
    const float* __restrict__ Xin,   // row stride OUTW (pre-offset)
    float* __restrict__ Xout,        // row stride OUTW (pre-offset)
    const int* __restrict__ batch,
    const float* __restrict__ W_node) {
    extern __shared__ float sh[];
    float* sW = sh;                       // 2D*D = 128KB
    float* sU = sh + 2 * D * D;           // 16*D = 8KB
    float* sV = sU + N_GRAPHS * D;        // 8 warps * 8 rows * 2D = 64KB
    for (int i = threadIdx.x; i < 2 * D * D; i += blockDim.x) sW[i] = W_node[i];
    for (int i = threadIdx.x; i < N_GRAPHS * D; i += blockDim.x) sU[i] = g_uWn3b[i];
    __syncthreads();
    int warp = threadIdx.x >> 5, lane = threadIdx.x & 31;
    float* myV = sV + warp * 8 * (2 * D);
    const int groups = N_NODES / 8;
    for (int grp = blockIdx.x * 8 + warp; grp < groups; grp += gridDim.x * 8) {
        int r0 = grp * 8;
#pragma unroll
        for (int e = 0; e < 8; e++) {
            int row = r0 + e;
            float4 xv = *((const float4*)(Xin + (size_t)row * OUTW) + lane);
            *((float4*)(myV + e * 2 * D) + lane) = xv;
            float inv = __ldg(&g_invN[row]);
            float4 av = __ldg((const float4*)(g_agg + (size_t)row * D) + lane);
            av.x *= inv; av.y *= inv; av.z *= inv; av.w *= inv;
            *((float4*)(myV + e * 2 * D + D) + lane) = av;
        }
        __syncwarp();
        float4 acc[8];
#pragma unroll
        for (int e = 0; e < 8; e++) acc[e] = make_float4(0.f, 0.f, 0.f, 0.f);
        for (int k = 0; k < 2 * D; k += 4) {
            float4 w0 = *((const float4*)(sW + (k + 0) * D) + lane);
            float4 w1 = *((const float4*)(sW + (k + 1) * D) + lane);
            float4 w2 = *((const float4*)(sW + (k + 2) * D) + lane);
            float4 w3 = *((const float4*)(sW + (k + 3) * D) + lane);
#pragma unroll
            for (int e = 0; e < 8; e++) {
                float4 a = *(const float4*)(myV + e * 2 * D + k);
                fma4x4(acc[e], a, w0, w1, w2, w3);
            }
        }
#pragma unroll
        for (int e = 0; e < 8; e++) {
            int row = r0 + e;
            int g = __ldg(batch + row);
            float4 ub = *((const float4*)(sU + g * D) + lane);
            float4 r;
            r.x = fmaxf(acc[e].x + ub.x, 0.f);
            r.y = fmaxf(acc[e].y + ub.y, 0.f);
            r.z = fmaxf(acc[e].z + ub.z, 0.f);
            r.w = fmaxf(acc[e].w + ub.w, 0.f);
            *((float4*)(Xout + (size_t)row * OUTW) + lane) = r;
            float* gs = g_gsum + g * D + lane * 4;
            atomicAdd(gs + 0, r.x);
            atomicAdd(gs + 1, r.y);
            atomicAdd(gs + 2, r.z);
            atomicAdd(gs + 3, r.w);
        }
        __syncwarp();
    }
}

// ------------------------------ global kernel ------------------------------
__global__ void global_kernel(const float* __restrict__ W_glob,
                              const float* __restrict__ b_glob,
                              float* __restrict__ out_g /* pre-offset, stride OUTW */) {
    __shared__ float su[N_GRAPHS * D];
    __shared__ float sm[N_GRAPHS * D];
    int tid = threadIdx.x;  // 128 threads
    for (int i = tid; i < N_GRAPHS * D; i += blockDim.x) {
        su[i] = g_u[i];
        sm[i] = g_gsum[i] * g_invG[i >> 7];
    }
    __syncthreads();
    int j = tid;
    float nu[N_GRAPHS];
#pragma unroll
    for (int g = 0; g < N_GRAPHS; g++) {
        float acc = b_glob[j];
        for (int k = 0; k < D; k++) acc = fmaf(su[g * D + k], W_glob[k * D + j], acc);
        for (int k = 0; k < D; k++) acc = fmaf(sm[g * D + k], W_glob[(D + k) * D + j], acc);
        nu[g] = fmaxf(acc, 0.f);
    }
    __syncthreads();
#pragma unroll
    for (int g = 0; g < N_GRAPHS; g++) {
        g_u[g * D + j] = nu[g];
        out_g[(size_t)g * OUTW + j] = nu[g];
    }
}

// --------------------------------- launch ----------------------------------
extern "C" void kernel_launch(void* const* d_in, const int* in_sizes, int n_in,
                              void* d_out, int out_size) {
    const float* x      = (const float*)d_in[0];
    const int*   ei     = (const int*)d_in[1];
    const float* ea     = (const float*)d_in[2];
    const float* u      = (const float*)d_in[3];
    const int*   batch  = (const int*)d_in[4];
    const float* W_edge = (const float*)d_in[5];
    const float* b_edge = (const float*)d_in[6];
    const float* W_node = (const float*)d_in[7];
    const float* b_node = (const float*)d_in[8];
    const float* W_glob = (const float*)d_in[9];
    const float* b_glob = (const float*)d_in[10];

    const int* src = ei;
    const int* dstp = ei + N_EDGES;

    float* out   = (float*)d_out;
    float* out_x = out;                            // 50000 x 512
    float* out_g = out + (size_t)N_NODES * OUTW;   // 16 x 512

    const int MV_SMEM   = (D * D + 4 * 8 * D) * 4;                        // 80 KB
    const int EDGE_SMEM = (D * D + N_GRAPHS * D + 4 * 8 * D) * 4;         // 88 KB
    const int NODE_SMEM = (2 * D * D + N_GRAPHS * D + 8 * 8 * 2 * D) * 4; // 200 KB

    cudaFuncSetAttribute(matvec_P_kernel, cudaFuncAttributeMaxDynamicSharedMemorySize, MV_SMEM);
    cudaFuncSetAttribute(edge_kernel,     cudaFuncAttributeMaxDynamicSharedMemorySize, EDGE_SMEM);
    cudaFuncSetAttribute(node_kernel,     cudaFuncAttributeMaxDynamicSharedMemorySize, NODE_SMEM);

    init_kernel<<<2048, 256>>>(x, u, out_x, out_g);
    hist_kernel<<<1024, 256>>>(dstp, batch);
    finalize_counts_kernel<<<256, 256>>>();

    for (int t = 0; t < 3; t++) {
        const float* Xt = out_x + t * D;        // current x, row stride OUTW
        float*       Xn = out_x + (t + 1) * D;  // next x

        prep_u_kernel<<<1, 128>>>(W_edge, b_edge, W_node, b_node);
        matvec_P_kernel<<<296, 128, MV_SMEM>>>(Xt, W_edge, 0);            // P1 = x@We1
        matvec_P_kernel<<<296, 128, MV_SMEM>>>(Xt, W_edge + D * D, D);    // P2 = x@We2
        zero_agg_kernel<<<2048, 256>>>();
        edge_kernel<<<296, 128, EDGE_SMEM>>>(t == 0 ? 1 : 0, ea, src, dstp, batch,
                                             W_edge + 2 * D * D);
        node_kernel<<<148, 256, NODE_SMEM>>>(Xt, Xn, batch, W_node);
        global_kernel<<<1, 128>>>(W_glob, b_glob, out_g + (t + 1) * D);
    }
}

// round 2
// speedup vs baseline: 1.6272x; 1.6272x over previous
#include <cuda_runtime.h>

// ---------------------------------------------------------------------------
// MetaMLP (3-step GraphNet / MetaLayer) on GB300 — FFMA2 (fma.rn.f32x2) version
// ---------------------------------------------------------------------------

#define D 128
static constexpr int N_NODES  = 50000;
static constexpr int N_EDGES  = 800000;
static constexpr int N_GRAPHS = 16;
static constexpr int OUTW     = 4 * D;   // 512 output columns per row

typedef unsigned long long u64;

// ------------------------- device scratch (no allocs) ----------------------
__device__ float g_ea  [(size_t)N_EDGES  * D];      // current edge features
__device__ float g_P12 [(size_t)N_NODES  * 2 * D];  // [P1 | P2] per node
__device__ float g_agg [(size_t)N_NODES  * D];      // sum of incoming ea'
__device__ float g_u    [N_GRAPHS * D];             // current u
__device__ float g_uW4b [N_GRAPHS * D];             // u@We4 + b_edge
__device__ float g_uWn3b[N_GRAPHS * D];             // u@Wn3 + b_node
__device__ float g_gsum [N_GRAPHS * D];             // per-graph node sums
__device__ float g_invN [N_NODES];                  // 1/max(in-degree,1)
__device__ float g_invG [N_GRAPHS];                 // 1/max(nodes per graph,1)

// ------------------------------ f32x2 helpers ------------------------------
__device__ __forceinline__ u64 pack2(float a, float b) {
    u64 r; asm("mov.b64 %0, {%1, %2};" : "=l"(r) : "f"(a), "f"(b)); return r;
}
__device__ __forceinline__ float2 unpack2(u64 v) {
    float2 r; asm("mov.b64 {%0, %1}, %2;" : "=f"(r.x), "=f"(r.y) : "l"(v)); return r;
}
__device__ __forceinline__ void ffma2(u64& d, u64 a, u64 b) {
    asm("fma.rn.f32x2 %0, %1, %2, %3;" : "=l"(d) : "l"(a), "l"(b), "l"(d));
}

// ------------------------------ init / counts ------------------------------
__global__ void init_kernel(const float* __restrict__ x, const float* __restrict__ u,
                            float* __restrict__ out_x, float* __restrict__ out_g) {
    int stride = gridDim.x * blockDim.x;
    int tid0 = blockIdx.x * blockDim.x + threadIdx.x;
    for (int i = tid0; i < N_NODES * D; i += stride) {
        int r = i >> 7, c = i & (D - 1);
        out_x[(size_t)r * OUTW + c] = x[i];
    }
    for (int i = tid0; i < N_GRAPHS * D; i += stride) {
        int r = i >> 7, c = i & (D - 1);
        out_g[(size_t)r * OUTW + c] = u[i];
        g_u[i] = u[i];
    }
    for (int i = tid0; i < N_NODES; i += stride) g_invN[i] = 0.f;
    for (int i = tid0; i < N_GRAPHS; i += stride) g_invG[i] = 0.f;
}

__global__ void hist_kernel(const int* __restrict__ dst, const int* __restrict__ batch) {
    int stride = gridDim.x * blockDim.x;
    int tid0 = blockIdx.x * blockDim.x + threadIdx.x;
    for (int i = tid0; i < N_EDGES; i += stride) atomicAdd(&g_invN[dst[i]], 1.f);
    for (int i = tid0; i < N_NODES; i += stride) atomicAdd(&g_invG[batch[i]], 1.f);
}

__global__ void finalize_counts_kernel() {
    int stride = gridDim.x * blockDim.x;
    int tid0 = blockIdx.x * blockDim.x + threadIdx.x;
    for (int i = tid0; i < N_NODES; i += stride) g_invN[i] = 1.f / fmaxf(g_invN[i], 1.f);
    for (int i = tid0; i < N_GRAPHS; i += stride) g_invG[i] = 1.f / fmaxf(g_invG[i], 1.f);
}

__global__ void zero_agg_kernel() {
    int stride = gridDim.x * blockDim.x;
    for (int i = blockIdx.x * blockDim.x + threadIdx.x; i < N_NODES * D; i += stride)
        g_agg[i] = 0.f;
}

// ------------------------ per-step small precompute -------------------------
// grid = 32 blocks: block b -> graph g = b>>1, matrix sel = b&1
// sel 0: g_uW4b[g] = u[g]@We4 + b_edge, and zero g_gsum[g]
// sel 1: g_uWn3b[g] = u[g]@Wn3 + b_node
__global__ void prep_u_kernel(const float* __restrict__ W_edge, const float* __restrict__ b_edge,
                              const float* __restrict__ W_node, const float* __restrict__ b_node) {
    int g = blockIdx.x >> 1, sel = blockIdx.x & 1;
    __shared__ float su[D];
    int j = threadIdx.x;
    su[j] = g_u[g * D + j];
    __syncthreads();
    const float* W = sel ? (W_node + 2 * D * D) : (W_edge + 3 * D * D);
    float acc = sel ? b_node[j] : b_edge[j];
#pragma unroll 8
    for (int k = 0; k < D; k++) acc = fmaf(su[k], W[k * D + j], acc);
    if (sel) {
        g_uWn3b[g * D + j] = acc;
    } else {
        g_uW4b[g * D + j] = acc;
        g_gsum[g * D + j] = 0.f;
    }
}

// ----------------- fused P1/P2 dense matvec (K=128, FFMA2) ------------------
// g_P12[row*256 + j]     = X[row] @ We1
// g_P12[row*256 + D + j] = X[row] @ We2
__global__ void __launch_bounds__(256) matvec_P_kernel(
    const float* __restrict__ X,   // row stride OUTW
    const float* __restrict__ W_edge) {
    extern __shared__ float sh[];
    float* sW1 = sh;               // D*D
    float* sW2 = sh + D * D;       // D*D
    float* sV  = sh + 2 * D * D;   // 8 warps * 8 rows * D
    for (int i = threadIdx.x; i < D * D; i += blockDim.x) {
        sW1[i] = W_edge[i];
        sW2[i] = W_edge[D * D + i];
    }
    __syncthreads();
    int warp = threadIdx.x >> 5, lane = threadIdx.x & 31;
    float* myV = sV + warp * 8 * D;
    const int groups = N_NODES / 8;
    for (int grp = blockIdx.x * 8 + warp; grp < groups; grp += gridDim.x * 8) {
        int r0 = grp * 8;
#pragma unroll
        for (int e = 0; e < 8; e++) {
            float4 v = *((const float4*)(X + (size_t)(r0 + e) * OUTW) + lane);
            *((float4*)(myV + e * D) + lane) = v;
        }
        __syncwarp();
        u64 a0[8], a1[8], b0[8], b1[8];
#pragma unroll
        for (int e = 0; e < 8; e++) { a0[e] = a1[e] = b0[e] = b1[e] = 0ull; }
        for (int k = 0; k < D; k += 4) {
            ulonglong2 u0 = *((const ulonglong2*)(sW1 + (k + 0) * D) + lane);
            ulonglong2 u1 = *((const ulonglong2*)(sW1 + (k + 1) * D) + lane);
            ulonglong2 u2 = *((const ulonglong2*)(sW1 + (k + 2) * D) + lane);
            ulonglong2 u3 = *((const ulonglong2*)(sW1 + (k + 3) * D) + lane);
            ulonglong2 v0 = *((const ulonglong2*)(sW2 + (k + 0) * D) + lane);
            ulonglong2 v1 = *((const ulonglong2*)(sW2 + (k + 1) * D) + lane);
            ulonglong2 v2 = *((const ulonglong2*)(sW2 + (k + 2) * D) + lane);
            ulonglong2 v3 = *((const ulonglong2*)(sW2 + (k + 3) * D) + lane);
#pragma unroll
            for (int e = 0; e < 8; e++) {
                float4 a = *(const float4*)(myV + e * D + k);
                u64 p;
                p = pack2(a.x, a.x);
                ffma2(a0[e], p, u0.x); ffma2(a1[e], p, u0.y);
                ffma2(b0[e], p, v0.x); ffma2(b1[e], p, v0.y);
                p = pack2(a.y, a.y);
                ffma2(a0[e], p, u1.x); ffma2(a1[e], p, u1.y);
                ffma2(b0[e], p, v1.x); ffma2(b1[e], p, v1.y);
                p = pack2(a.z, a.z);
                ffma2(a0[e], p, u2.x); ffma2(a1[e], p, u2.y);
                ffma2(b0[e], p, v2.x); ffma2(b1[e], p, v2.y);
                p = pack2(a.w, a.w);
                ffma2(a0[e], p, u3.x); ffma2(a1[e], p, u3.y);
                ffma2(b0[e], p, v3.x); ffma2(b1[e], p, v3.y);
            }
        }
#pragma unroll
        for (int e = 0; e < 8; e++) {
            float2 r01 = unpack2(a0[e]), r23 = unpack2(a1[e]);
            float2 s01 = unpack2(b0[e]), s23 = unpack2(b1[e]);
            float* base = g_P12 + (size_t)(r0 + e) * (2 * D);
            *((float4*)base + lane)       = make_float4(r01.x, r01.y, r23.x, r23.y);
            *((float4*)(base + D) + lane) = make_float4(s01.x, s01.y, s23.x, s23.y);
        }
        __syncwarp();
    }
}

// ------------------------------- edge kernel -------------------------------
// ea' = relu(P1[src] + P2[dst] + ea@We3 + uW4b[batch[src]]); scatter-add to agg
__global__ void __launch_bounds__(256) edge_kernel(
    int use_ext, const float* __restrict__ ext_ea,
    const int* __restrict__ src, const int* __restrict__ dst,
    const int* __restrict__ batch,
    const float* __restrict__ We3) {
    extern __shared__ float sh[];
    float* sW  = sh;                      // D*D
    float* sU  = sh + D * D;              // 16*D
    float* sEA = sU + N_GRAPHS * D;       // 8 warps * 8 rows * D
    for (int i = threadIdx.x; i < D * D; i += blockDim.x) sW[i] = We3[i];
    for (int i = threadIdx.x; i < N_GRAPHS * D; i += blockDim.x) sU[i] = g_uW4b[i];
    __syncthreads();
    const float* ea_in = use_ext ? ext_ea : (const float*)g_ea;
    int warp = threadIdx.x >> 5, lane = threadIdx.x & 31;
    float* myEA = sEA + warp * 8 * D;
    const int groups = N_EDGES / 8;
    for (int grp = blockIdx.x * 8 + warp; grp < groups; grp += gridDim.x * 8) {
        int e0 = grp * 8;
#pragma unroll
        for (int e = 0; e < 8; e++) {
            float4 v = *((const float4*)(ea_in + (size_t)(e0 + e) * D) + lane);
            *((float4*)(myEA + e * D) + lane) = v;
        }
        __syncwarp();
        u64 acc0[8], acc1[8];
#pragma unroll
        for (int e = 0; e < 8; e++) { acc0[e] = 0ull; acc1[e] = 0ull; }
        for (int k = 0; k < D; k += 4) {
            ulonglong2 w0 = *((const ulonglong2*)(sW + (k + 0) * D) + lane);
            ulonglong2 w1 = *((const ulonglong2*)(sW + (k + 1) * D) + lane);
            ulonglong2 w2 = *((const ulonglong2*)(sW + (k + 2) * D) + lane);
            ulonglong2 w3 = *((const ulonglong2*)(sW + (k + 3) * D) + lane);
#pragma unroll
            for (int e = 0; e < 8; e++) {
                float4 a = *(const float4*)(myEA + e * D + k);
                u64 p;
                p = pack2(a.x, a.x); ffma2(acc0[e], p, w0.x); ffma2(acc1[e], p, w0.y);
                p = pack2(a.y, a.y); ffma2(acc0[e], p, w1.x); ffma2(acc1[e], p, w1.y);
                p = pack2(a.z, a.z); ffma2(acc0[e], p, w2.x); ffma2(acc1[e], p, w2.y);
                p = pack2(a.w, a.w); ffma2(acc0[e], p, w3.x); ffma2(acc1[e], p, w3.y);
            }
        }
#pragma unroll
        for (int e = 0; e < 8; e++) {
            int ei = e0 + e;
            int s = __ldg(src + ei);
            int d = __ldg(dst + ei);
            int g = __ldg(batch + s);
            float4 p1 = __ldg((const float4*)(g_P12 + (size_t)s * (2 * D)) + lane);
            float4 p2 = __ldg((const float4*)(g_P12 + (size_t)d * (2 * D) + D) + lane);
            float4 ub = *((const float4*)(sU + g * D) + lane);
            float2 c01 = unpack2(acc0[e]), c23 = unpack2(acc1[e]);
            float4 r;
            r.x = fmaxf(c01.x + p1.x + p2.x + ub.x, 0.f);
            r.y = fmaxf(c01.y + p1.y + p2.y + ub.y, 0.f);
            r.z = fmaxf(c23.x + p1.z + p2.z + ub.z, 0.f);
            r.w = fmaxf(c23.y + p1.w + p2.w + ub.w, 0.f);
            *((float4*)(g_ea + (size_t)ei * D) + lane) = r;
            atomicAdd((float4*)(g_agg + (size_t)d * D) + lane, r);
        }
        __syncwarp();
    }
}

// ------------------------------- node kernel -------------------------------
// x' = relu([x, agg] @ Wn12 + uWn3b[batch]); accumulate per-graph sums
__global__ void __launch_bounds__(256) node_kernel(
    const float* __restrict__ Xin,   // row stride OUTW (pre-offset)
    float* __restrict__ Xout,        // row stride OUTW (pre-offset)
    const int* __restrict__ batch,
    const float* __restrict__ W_node) {
    extern __shared__ float sh[];
    float* sW = sh;                       // 2D*D
    float* sU = sh + 2 * D * D;           // 16*D
    float* sV = sU + N_GRAPHS * D;        // 8 warps * 8 rows * 2D
    for (int i = threadIdx.x; i < 2 * D * D; i += blockDim.x) sW[i] = W_node[i];
    for (int i = threadIdx.x; i < N_GRAPHS * D; i += blockDim.x) sU[i] = g_uWn3b[i];
    __syncthreads();
    int warp = threadIdx.x >> 5, lane = threadIdx.x & 31;
    float* myV = sV + warp * 8 * (2 * D);
    const int groups = N_NODES / 8;
    for (int grp = blockIdx.x * 8 + warp; grp < groups; grp += gridDim.x * 8) {
        int r0 = grp * 8;
#pragma unroll
        for (int e = 0; e < 8; e++) {
            int row = r0 + e;
            float4 xv = *((const float4*)(Xin + (size_t)row * OUTW) + lane);
            *((float4*)(myV + e * 2 * D) + lane) = xv;
            float inv = __ldg(&g_invN[row]);
            float4 av = __ldg((const float4*)(g_agg + (size_t)row * D) + lane);
            av.x *= inv; av.y *= inv; av.z *= inv; av.w *= inv;
            *((float4*)(myV + e * 2 * D + D) + lane) = av;
        }
        __syncwarp();
        u64 acc0[8], acc1[8];
#pragma unroll
        for (int e = 0; e < 8; e++) { acc0[e] = 0ull; acc1[e] = 0ull; }
        for (int k = 0; k < 2 * D; k += 4) {
            ulonglong2 w0 = *((const ulonglong2*)(sW + (k + 0) * D) + lane);
            ulonglong2 w1 = *((const ulonglong2*)(sW + (k + 1) * D) + lane);
            ulonglong2 w2 = *((const ulonglong2*)(sW + (k + 2) * D) + lane);
            ulonglong2 w3 = *((const ulonglong2*)(sW + (k + 3) * D) + lane);
#pragma unroll
            for (int e = 0; e < 8; e++) {
                float4 a = *(const float4*)(myV + e * 2 * D + k);
                u64 p;
                p = pack2(a.x, a.x); ffma2(acc0[e], p, w0.x); ffma2(acc1[e], p, w0.y);
                p = pack2(a.y, a.y); ffma2(acc0[e], p, w1.x); ffma2(acc1[e], p, w1.y);
                p = pack2(a.z, a.z); ffma2(acc0[e], p, w2.x); ffma2(acc1[e], p, w2.y);
                p = pack2(a.w, a.w); ffma2(acc0[e], p, w3.x); ffma2(acc1[e], p, w3.y);
            }
        }
#pragma unroll
        for (int e = 0; e < 8; e++) {
            int row = r0 + e;
            int g = __ldg(batch + row);
            float4 ub = *((const float4*)(sU + g * D) + lane);
            float2 c01 = unpack2(acc0[e]), c23 = unpack2(acc1[e]);
            float4 r;
            r.x = fmaxf(c01.x + ub.x, 0.f);
            r.y = fmaxf(c01.y + ub.y, 0.f);
            r.z = fmaxf(c23.x + ub.z, 0.f);
            r.w = fmaxf(c23.y + ub.w, 0.f);
            *((float4*)(Xout + (size_t)row * OUTW) + lane) = r;
            atomicAdd((float4*)(g_gsum + g * D) + lane, r);
        }
        __syncwarp();
    }
}

// ------------------------------ global kernel ------------------------------
// grid = 16 (one block per graph), 128 threads
__global__ void global_kernel(const float* __restrict__ W_glob,
                              const float* __restrict__ b_glob,
                              float* __restrict__ out_g /* pre-offset, stride OUTW */) {
    int g = blockIdx.x;
    int j = threadIdx.x;
    __shared__ float su[D], sm[D];
    su[j] = g_u[g * D + j];
    sm[j] = g_gsum[g * D + j] * g_invG[g];
    __syncthreads();
    float acc = b_glob[j];
#pragma unroll 4
    for (int k = 0; k < D; k++) acc = fmaf(su[k], W_glob[k * D + j], acc);
#pragma unroll 4
    for (int k = 0; k < D; k++) acc = fmaf(sm[k], W_glob[(D + k) * D + j], acc);
    float r = fmaxf(acc, 0.f);
    out_g[(size_t)g * OUTW + j] = r;
    g_u[g * D + j] = r;
}

// --------------------------------- launch ----------------------------------
extern "C" void kernel_launch(void* const* d_in, const int* in_sizes, int n_in,
                              void* d_out, int out_size) {
    const float* x      = (const float*)d_in[0];
    const int*   ei     = (const int*)d_in[1];
    const float* ea     = (const float*)d_in[2];
    const float* u      = (const float*)d_in[3];
    const int*   batch  = (const int*)d_in[4];
    const float* W_edge = (const float*)d_in[5];
    const float* b_edge = (const float*)d_in[6];
    const float* W_node = (const float*)d_in[7];
    const float* b_node = (const float*)d_in[8];
    const float* W_glob = (const float*)d_in[9];
    const float* b_glob = (const float*)d_in[10];

    const int* src = ei;
    const int* dstp = ei + N_EDGES;

    float* out   = (float*)d_out;
    float* out_x = out;                            // 50000 x 512
    float* out_g = out + (size_t)N_NODES * OUTW;   // 16 x 512

    const int MV_SMEM   = (2 * D * D + 8 * 8 * D) * 4;                       // 160 KB
    const int EDGE_SMEM = (D * D + N_GRAPHS * D + 8 * 8 * D) * 4;            // 104 KB
    const int NODE_SMEM = (2 * D * D + N_GRAPHS * D + 8 * 8 * 2 * D) * 4;    // 200 KB

    cudaFuncSetAttribute(matvec_P_kernel, cudaFuncAttributeMaxDynamicSharedMemorySize, MV_SMEM);
    cudaFuncSetAttribute(edge_kernel,     cudaFuncAttributeMaxDynamicSharedMemorySize, EDGE_SMEM);
    cudaFuncSetAttribute(node_kernel,     cudaFuncAttributeMaxDynamicSharedMemorySize, NODE_SMEM);

    init_kernel<<<2048, 256>>>(x, u, out_x, out_g);
    hist_kernel<<<1024, 256>>>(dstp, batch);
    finalize_counts_kernel<<<256, 256>>>();

    for (int t = 0; t < 3; t++) {
        const float* Xt = out_x + t * D;        // current x, row stride OUTW
        float*       Xn = out_x + (t + 1) * D;  // next x

        prep_u_kernel<<<32, 128>>>(W_edge, b_edge, W_node, b_node);
        matvec_P_kernel<<<148, 256, MV_SMEM>>>(Xt, W_edge);
        zero_agg_kernel<<<2048, 256>>>();
        edge_kernel<<<296, 256, EDGE_SMEM>>>(t == 0 ? 1 : 0, ea, src, dstp, batch,
                                             W_edge + 2 * D * D);
        node_kernel<<<148, 256, NODE_SMEM>>>(Xt, Xn, batch, W_node);
        global_kernel<<<16, 128>>>(W_glob, b_glob, out_g + (t + 1) * D);
    }
}

// round 4
// speedup vs baseline: 2.1401x; 1.3152x over previous
#include <cuda_runtime.h>
#include <cstdint>

// ---------------------------------------------------------------------------
// MetaMLP (3-step GraphNet) on GB300 — mma.sync bf16-split edge GEMM.
// (tcgen05 unavailable: harness ptxas targets plain sm_103)
// ---------------------------------------------------------------------------

#define D 128
static constexpr int N_NODES  = 50000;
static constexpr int N_EDGES  = 800000;
static constexpr int N_GRAPHS = 16;
static constexpr int OUTW     = 4 * D;          // 512 output cols per row
static constexpr int N_TILES  = N_EDGES / 128;  // 6250

typedef unsigned long long u64;

// ------------------------- device scratch (no allocs) ----------------------
__device__ float g_ea  [(size_t)N_EDGES  * D];
__device__ float g_P12 [(size_t)N_NODES  * 2 * D];   // [P1+u+b | P2]
__device__ float g_agg [(size_t)N_NODES  * D];
__device__ float g_u    [N_GRAPHS * D];
__device__ float g_uW4b [N_GRAPHS * D];
__device__ float g_uWn3b[N_GRAPHS * D];
__device__ float g_gsum [N_GRAPHS * D];
__device__ float g_invN [N_NODES];
__device__ float g_invG [N_GRAPHS];

// ------------------------------ helpers ------------------------------------
__device__ __forceinline__ u64 pack2(float a, float b) {
    u64 r; asm("mov.b64 %0, {%1, %2};" : "=l"(r) : "f"(a), "f"(b)); return r;
}
__device__ __forceinline__ float2 unpack2(u64 v) {
    float2 r; asm("mov.b64 {%0, %1}, %2;" : "=f"(r.x), "=f"(r.y) : "l"(v)); return r;
}
__device__ __forceinline__ void ffma2(u64& d, u64 a, u64 b) {
    asm("fma.rn.f32x2 %0, %1, %2, %3;" : "=l"(d) : "l"(a), "l"(b), "l"(d));
}

// pack two floats to bf16x2 (lo half = a, hi half = b)
__device__ __forceinline__ uint32_t cvt_bf16x2(float a, float b) {
    uint32_t r;
    asm("cvt.rn.bf16x2.f32 %0, %1, %2;" : "=r"(r) : "f"(b), "f"(a));
    return r;
}
// split (v.x, v.y) into bf16x2 hi + bf16x2 lo residual
__device__ __forceinline__ void split2(float x, float y, uint32_t& hi, uint32_t& lo) {
    hi = cvt_bf16x2(x, y);
    float hx = __uint_as_float(hi << 16);
    float hy = __uint_as_float(hi & 0xffff0000u);
    lo = cvt_bf16x2(x - hx, y - hy);
}

// m16n8k16 row.col bf16 MMA, f32 accumulate in-place
__device__ __forceinline__ void mma_bf16(float* d, const uint32_t* a, uint32_t b0, uint32_t b1) {
    asm volatile("mma.sync.aligned.m16n8k16.row.col.f32.bf16.bf16.f32 "
        "{%0,%1,%2,%3}, {%4,%5,%6,%7}, {%8,%9}, {%0,%1,%2,%3};"
        : "+f"(d[0]), "+f"(d[1]), "+f"(d[2]), "+f"(d[3])
        : "r"(a[0]), "r"(a[1]), "r"(a[2]), "r"(a[3]), "r"(b0), "r"(b1));
}

__device__ __forceinline__ void red_add2(float* addr, float x, float y) {
    asm volatile("red.global.add.v2.f32 [%0], {%1, %2};"
                 :: "l"(addr), "f"(x), "f"(y) : "memory");
}

// ------------------------------ init / counts ------------------------------
__global__ void init_kernel(const float* __restrict__ x, const float* __restrict__ u,
                            float* __restrict__ out_x, float* __restrict__ out_g) {
    int stride = gridDim.x * blockDim.x;
    int tid0 = blockIdx.x * blockDim.x + threadIdx.x;
    for (int i = tid0; i < N_NODES * D; i += stride) {
        int r = i >> 7, c = i & (D - 1);
        out_x[(size_t)r * OUTW + c] = x[i];
        g_agg[i] = 0.f;
    }
    for (int i = tid0; i < N_GRAPHS * D; i += stride) {
        int r = i >> 7, c = i & (D - 1);
        out_g[(size_t)r * OUTW + c] = u[i];
        g_u[i] = u[i];
    }
    for (int i = tid0; i < N_NODES; i += stride) g_invN[i] = 0.f;
    for (int i = tid0; i < N_GRAPHS; i += stride) g_invG[i] = 0.f;
}

__global__ void hist_kernel(const int* __restrict__ dst, const int* __restrict__ batch) {
    int stride = gridDim.x * blockDim.x;
    int tid0 = blockIdx.x * blockDim.x + threadIdx.x;
    for (int i = tid0; i < N_EDGES; i += stride) atomicAdd(&g_invN[dst[i]], 1.f);
    for (int i = tid0; i < N_NODES; i += stride) atomicAdd(&g_invG[batch[i]], 1.f);
}

__global__ void finalize_counts_kernel() {
    int stride = gridDim.x * blockDim.x;
    int tid0 = blockIdx.x * blockDim.x + threadIdx.x;
    for (int i = tid0; i < N_NODES; i += stride) g_invN[i] = 1.f / fmaxf(g_invN[i], 1.f);
    for (int i = tid0; i < N_GRAPHS; i += stride) g_invG[i] = 1.f / fmaxf(g_invG[i], 1.f);
}

// ------------------------ per-step small precompute -------------------------
__global__ void prep_u_kernel(const float* __restrict__ W_edge, const float* __restrict__ b_edge,
                              const float* __restrict__ W_node, const float* __restrict__ b_node) {
    int g = blockIdx.x >> 1, sel = blockIdx.x & 1;
    __shared__ float su[D];
    int j = threadIdx.x;
    su[j] = g_u[g * D + j];
    __syncthreads();
    const float* W = sel ? (W_node + 2 * D * D) : (W_edge + 3 * D * D);
    float acc = sel ? b_node[j] : b_edge[j];
#pragma unroll 8
    for (int k = 0; k < D; k++) acc = fmaf(su[k], W[k * D + j], acc);
    if (sel) {
        g_uWn3b[g * D + j] = acc;
    } else {
        g_uW4b[g * D + j] = acc;
        g_gsum[g * D + j] = 0.f;
    }
}

// ----------------- fused P1/P2 dense matvec (K=128, FFMA2) ------------------
// P1 = X@We1 + uW4b[batch]  (edge-u term folded in);  P2 = X@We2
__global__ void __launch_bounds__(256) matvec_P_kernel(
    const float* __restrict__ X, const float* __restrict__ W_edge,
    const int* __restrict__ batch) {
    extern __shared__ float sh[];
    float* sW1 = sh;
    float* sW2 = sh + D * D;
    float* sV  = sh + 2 * D * D;
    for (int i = threadIdx.x; i < D * D; i += blockDim.x) {
        sW1[i] = W_edge[i];
        sW2[i] = W_edge[D * D + i];
    }
    __syncthreads();
    int warp = threadIdx.x >> 5, lane = threadIdx.x & 31;
    float* myV = sV + warp * 8 * D;
    const int groups = N_NODES / 8;
    for (int grp = blockIdx.x * 8 + warp; grp < groups; grp += gridDim.x * 8) {
        int r0 = grp * 8;
#pragma unroll
        for (int e = 0; e < 8; e++) {
            float4 v = *((const float4*)(X + (size_t)(r0 + e) * OUTW) + lane);
            *((float4*)(myV + e * D) + lane) = v;
        }
        __syncwarp();
        u64 a0[8], a1[8], b0[8], b1[8];
#pragma unroll
        for (int e = 0; e < 8; e++) { a0[e] = a1[e] = b0[e] = b1[e] = 0ull; }
        for (int k = 0; k < D; k += 4) {
            ulonglong2 u0 = *((const ulonglong2*)(sW1 + (k + 0) * D) + lane);
            ulonglong2 u1 = *((const ulonglong2*)(sW1 + (k + 1) * D) + lane);
            ulonglong2 u2 = *((const ulonglong2*)(sW1 + (k + 2) * D) + lane);
            ulonglong2 u3 = *((const ulonglong2*)(sW1 + (k + 3) * D) + lane);
            ulonglong2 v0 = *((const ulonglong2*)(sW2 + (k + 0) * D) + lane);
            ulonglong2 v1 = *((const ulonglong2*)(sW2 + (k + 1) * D) + lane);
            ulonglong2 v2 = *((const ulonglong2*)(sW2 + (k + 2) * D) + lane);
            ulonglong2 v3 = *((const ulonglong2*)(sW2 + (k + 3) * D) + lane);
#pragma unroll
            for (int e = 0; e < 8; e++) {
                float4 a = *(const float4*)(myV + e * D + k);
                u64 p;
                p = pack2(a.x, a.x);
                ffma2(a0[e], p, u0.x); ffma2(a1[e], p, u0.y);
                ffma2(b0[e], p, v0.x); ffma2(b1[e], p, v0.y);
                p = pack2(a.y, a.y);
                ffma2(a0[e], p, u1.x); ffma2(a1[e], p, u1.y);
                ffma2(b0[e], p, v1.x); ffma2(b1[e], p, v1.y);
                p = pack2(a.z, a.z);
                ffma2(a0[e], p, u2.x); ffma2(a1[e], p, u2.y);
                ffma2(b0[e], p, v2.x); ffma2(b1[e], p, v2.y);
                p = pack2(a.w, a.w);
                ffma2(a0[e], p, u3.x); ffma2(a1[e], p, u3.y);
                ffma2(b0[e], p, v3.x); ffma2(b1[e], p, v3.y);
            }
        }
#pragma unroll
        for (int e = 0; e < 8; e++) {
            int g = __ldg(batch + r0 + e);
            float4 uv = *((const float4*)(g_uW4b + g * D) + lane);
            float2 r01 = unpack2(a0[e]), r23 = unpack2(a1[e]);
            float2 s01 = unpack2(b0[e]), s23 = unpack2(b1[e]);
            float* base = g_P12 + (size_t)(r0 + e) * (2 * D);
            *((float4*)base + lane) =
                make_float4(r01.x + uv.x, r01.y + uv.y, r23.x + uv.z, r23.y + uv.w);
            *((float4*)(base + D) + lane) = make_float4(s01.x, s01.y, s23.x, s23.y);
        }
        __syncwarp();
    }
}

// ------------------------- edge kernel: mma.sync ----------------------------
// ea' = relu(ea@We3 + P1'[src] + P2[dst]); scatter-add to agg.
// bf16 2-way split: D = Ahi*Whi + Ahi*Wlo + Alo*Whi (fp32 accumulate).
// Warp tiling: 8 warps = 4 m-slices (32 rows) x 2 n-halves (64 cols).
__global__ void __launch_bounds__(256, 2) edge_mma_kernel(
    int use_ext, int store_ea, const float* __restrict__ ext_ea,
    const int* __restrict__ src, const int* __restrict__ dst,
    const float* __restrict__ We3) {
    extern __shared__ uint4 sB[];   // [nt=16][ks=8][lane=32] -> {b0hi,b1hi,b0lo,b1lo}
    int tid = threadIdx.x;

    // --- pre-pack W fragments (hi/lo split), once per block ---
    for (int i = tid; i < 16 * 8 * 32; i += 256) {
        int lane = i & 31, ks = (i >> 5) & 7, nt = i >> 8;
        int gid = lane >> 2, tig = lane & 3;
        int n  = nt * 8 + gid;
        int k0 = ks * 16 + tig * 2;
        float w00 = __ldg(We3 + k0 * D + n);
        float w01 = __ldg(We3 + (k0 + 1) * D + n);
        float w10 = __ldg(We3 + (k0 + 8) * D + n);
        float w11 = __ldg(We3 + (k0 + 9) * D + n);
        uint32_t b0h, b0l, b1h, b1l;
        split2(w00, w01, b0h, b0l);
        split2(w10, w11, b1h, b1l);
        sB[i] = make_uint4(b0h, b1h, b0l, b1l);
    }
    __syncthreads();

    int wid = tid >> 5, lane = tid & 31;
    int gid = lane >> 2, tig = lane & 3;
    int wm = wid & 3, wn = wid >> 2;
    const float* ea_in = use_ext ? ext_ea : (const float*)g_ea;

    for (int tile = blockIdx.x; tile < N_TILES; tile += gridDim.x) {
        const float* A = ea_in + (size_t)tile * (128 * 128);
        float acc[2][8][4];
#pragma unroll
        for (int mt = 0; mt < 2; mt++)
#pragma unroll
            for (int nt = 0; nt < 8; nt++)
#pragma unroll
                for (int q = 0; q < 4; q++) acc[mt][nt][q] = 0.f;

#pragma unroll
        for (int ks = 0; ks < 8; ks++) {
            uint32_t ah[2][4], al[2][4];
#pragma unroll
            for (int mt = 0; mt < 2; mt++) {
                const float* p = A + (wm * 32 + mt * 16 + gid) * 128 + ks * 16 + tig * 2;
                float2 v0 = __ldg((const float2*)p);
                float2 v1 = __ldg((const float2*)(p + 8 * 128));
                float2 v2 = __ldg((const float2*)(p + 8));
                float2 v3 = __ldg((const float2*)(p + 8 * 128 + 8));
                split2(v0.x, v0.y, ah[mt][0], al[mt][0]);
                split2(v1.x, v1.y, ah[mt][1], al[mt][1]);
                split2(v2.x, v2.y, ah[mt][2], al[mt][2]);
                split2(v3.x, v3.y, ah[mt][3], al[mt][3]);
            }
#pragma unroll
            for (int nt = 0; nt < 8; nt++) {
                uint4 b = sB[((wn * 8 + nt) * 8 + ks) * 32 + lane];
#pragma unroll
                for (int mt = 0; mt < 2; mt++) {
                    mma_bf16(acc[mt][nt], ah[mt], b.x, b.y);   // Ahi * Whi
                    mma_bf16(acc[mt][nt], ah[mt], b.z, b.w);   // Ahi * Wlo
                    mma_bf16(acc[mt][nt], al[mt], b.x, b.y);   // Alo * Whi
                }
            }
        }

        // --- epilogue: D frag layout; rows = edges, col pairs 2tig ---
#pragma unroll
        for (int mt = 0; mt < 2; mt++) {
#pragma unroll
            for (int h = 0; h < 2; h++) {
                int r = tile * 128 + wm * 32 + mt * 16 + h * 8 + gid;
                int s = __ldg(src + r), d = __ldg(dst + r);
                const float* p1b = g_P12 + (size_t)s * 256;
                const float* p2b = g_P12 + (size_t)d * 256 + 128;
                float* eo = g_ea + (size_t)r * 128;
                float* ao = g_agg + (size_t)d * 128;
#pragma unroll
                for (int nt = 0; nt < 8; nt++) {
                    int c = wn * 64 + nt * 8 + tig * 2;
                    float2 p1 = __ldg((const float2*)(p1b + c));
                    float2 p2 = __ldg((const float2*)(p2b + c));
                    float rx = fmaxf(acc[mt][nt][h * 2 + 0] + p1.x + p2.x, 0.f);
                    float ry = fmaxf(acc[mt][nt][h * 2 + 1] + p1.y + p2.y, 0.f);
                    if (store_ea) *(float2*)(eo + c) = make_float2(rx, ry);
                    red_add2(ao + c, rx, ry);
                }
            }
        }
    }
}

// ------------------------------- node kernel -------------------------------
__global__ void __launch_bounds__(256) node_kernel(
    const float* __restrict__ Xin, float* __restrict__ Xout,
    const int* __restrict__ batch, const float* __restrict__ W_node) {
    extern __shared__ float sh[];
    float* sW = sh;
    float* sU = sh + 2 * D * D;
    float* sV = sU + N_GRAPHS * D;
    for (int i = threadIdx.x; i < 2 * D * D; i += blockDim.x) sW[i] = W_node[i];
    for (int i = threadIdx.x; i < N_GRAPHS * D; i += blockDim.x) sU[i] = g_uWn3b[i];
    __syncthreads();
    int warp = threadIdx.x >> 5, lane = threadIdx.x & 31;
    float* myV = sV + warp * 8 * (2 * D);
    const int groups = N_NODES / 8;
    for (int grp = blockIdx.x * 8 + warp; grp < groups; grp += gridDim.x * 8) {
        int r0 = grp * 8;
#pragma unroll
        for (int e = 0; e < 8; e++) {
            int row = r0 + e;
            float4 xv = *((const float4*)(Xin + (size_t)row * OUTW) + lane);
            *((float4*)(myV + e * 2 * D) + lane) = xv;
            float inv = __ldg(&g_invN[row]);
            float4 av = *((const float4*)(g_agg + (size_t)row * D) + lane);
            // zero agg for next step (this kernel is its only reader)
            *((float4*)(g_agg + (size_t)row * D) + lane) = make_float4(0.f, 0.f, 0.f, 0.f);
            av.x *= inv; av.y *= inv; av.z *= inv; av.w *= inv;
            *((float4*)(myV + e * 2 * D + D) + lane) = av;
        }
        __syncwarp();
        u64 acc0[8], acc1[8];
#pragma unroll
        for (int e = 0; e < 8; e++) { acc0[e] = 0ull; acc1[e] = 0ull; }
        for (int k = 0; k < 2 * D; k += 4) {
            ulonglong2 w0 = *((const ulonglong2*)(sW + (k + 0) * D) + lane);
            ulonglong2 w1 = *((const ulonglong2*)(sW + (k + 1) * D) + lane);
            ulonglong2 w2 = *((const ulonglong2*)(sW + (k + 2) * D) + lane);
            ulonglong2 w3 = *((const ulonglong2*)(sW + (k + 3) * D) + lane);
#pragma unroll
            for (int e = 0; e < 8; e++) {
                float4 a = *(const float4*)(myV + e * 2 * D + k);
                u64 p;
                p = pack2(a.x, a.x); ffma2(acc0[e], p, w0.x); ffma2(acc1[e], p, w0.y);
                p = pack2(a.y, a.y); ffma2(acc0[e], p, w1.x); ffma2(acc1[e], p, w1.y);
                p = pack2(a.z, a.z); ffma2(acc0[e], p, w2.x); ffma2(acc1[e], p, w2.y);
                p = pack2(a.w, a.w); ffma2(acc0[e], p, w3.x); ffma2(acc1[e], p, w3.y);
            }
        }
#pragma unroll
        for (int e = 0; e < 8; e++) {
            int row = r0 + e;
            int g = __ldg(batch + row);
            float4 ub = *((const float4*)(sU + g * D) + lane);
            float2 c01 = unpack2(acc0[e]), c23 = unpack2(acc1[e]);
            float4 r;
            r.x = fmaxf(c01.x + ub.x, 0.f);
            r.y = fmaxf(c01.y + ub.y, 0.f);
            r.z = fmaxf(c23.x + ub.z, 0.f);
            r.w = fmaxf(c23.y + ub.w, 0.f);
            *((float4*)(Xout + (size_t)row * OUTW) + lane) = r;
            atomicAdd((float4*)(g_gsum + g * D) + lane, r);
        }
        __syncwarp();
    }
}

// ------------------------------ global kernel ------------------------------
__global__ void global_kernel(const float* __restrict__ W_glob,
                              const float* __restrict__ b_glob,
                              float* __restrict__ out_g) {
    int g = blockIdx.x;
    int j = threadIdx.x;
    __shared__ float su[D], sm[D];
    su[j] = g_u[g * D + j];
    sm[j] = g_gsum[g * D + j] * g_invG[g];
    __syncthreads();
    float acc = b_glob[j];
#pragma unroll 4
    for (int k = 0; k < D; k++) acc = fmaf(su[k], W_glob[k * D + j], acc);
#pragma unroll 4
    for (int k = 0; k < D; k++) acc = fmaf(sm[k], W_glob[(D + k) * D + j], acc);
    float r = fmaxf(acc, 0.f);
    out_g[(size_t)g * OUTW + j] = r;
    g_u[g * D + j] = r;
}

// --------------------------------- launch ----------------------------------
extern "C" void kernel_launch(void* const* d_in, const int* in_sizes, int n_in,
                              void* d_out, int out_size) {
    const float* x      = (const float*)d_in[0];
    const int*   ei     = (const int*)d_in[1];
    const float* ea     = (const float*)d_in[2];
    const float* u      = (const float*)d_in[3];
    const int*   batch  = (const int*)d_in[4];
    const float* W_edge = (const float*)d_in[5];
    const float* b_edge = (const float*)d_in[6];
    const float* W_node = (const float*)d_in[7];
    const float* b_node = (const float*)d_in[8];
    const float* W_glob = (const float*)d_in[9];
    const float* b_glob = (const float*)d_in[10];

    const int* src = ei;
    const int* dstp = ei + N_EDGES;

    float* out   = (float*)d_out;
    float* out_x = out;                            // 50000 x 512
    float* out_g = out + (size_t)N_NODES * OUTW;   // 16 x 512

    const int MV_SMEM   = (2 * D * D + 8 * 8 * D) * 4;                       // 160 KB
    const int EDGE_SMEM = 16 * 8 * 32 * 16;                                  // 64 KB
    const int NODE_SMEM = (2 * D * D + N_GRAPHS * D + 8 * 8 * 2 * D) * 4;    // 200 KB

    cudaFuncSetAttribute(matvec_P_kernel, cudaFuncAttributeMaxDynamicSharedMemorySize, MV_SMEM);
    cudaFuncSetAttribute(edge_mma_kernel, cudaFuncAttributeMaxDynamicSharedMemorySize, EDGE_SMEM);
    cudaFuncSetAttribute(node_kernel,     cudaFuncAttributeMaxDynamicSharedMemorySize, NODE_SMEM);

    init_kernel<<<2048, 256>>>(x, u, out_x, out_g);
    hist_kernel<<<1024, 256>>>(dstp, batch);
    finalize_counts_kernel<<<256, 256>>>();

    for (int t = 0; t < 3; t++) {
        const float* Xt = out_x + t * D;
        float*       Xn = out_x + (t + 1) * D;

        prep_u_kernel<<<32, 128>>>(W_edge, b_edge, W_node, b_node);
        matvec_P_kernel<<<148, 256, MV_SMEM>>>(Xt, W_edge, batch);
        edge_mma_kernel<<<296, 256, EDGE_SMEM>>>(t == 0 ? 1 : 0, t < 2 ? 1 : 0, ea,
                                                 src, dstp, W_edge + 2 * D * D);
        node_kernel<<<148, 256, NODE_SMEM>>>(Xt, Xn, batch, W_node);
        global_kernel<<<16, 128>>>(W_glob, b_glob, out_g + (t + 1) * D);
    }
}